// round 14
// baseline (speedup 1.0000x reference)
#include <cuda_runtime.h>
#include <cuda_bf16.h>
#include <cstdint>
#include <cstdio>

#define BB  8
#define NP  2048
#define KNN 20
#define NEG_INF (-3.4e38f)
#define ASTR 40
#define XROWS 512
#define CHB 4            // batches per dist/topk chunk (67MB slice, L2-resident)

typedef unsigned long long u64t;

// ---------------- f32x2 packed-FMA helpers ----------------
__device__ __forceinline__ u64t pk2(float lo, float hi) {
    u64t d; asm("mov.b64 %0,{%1,%2};" : "=l"(d) : "f"(lo), "f"(hi)); return d;
}
__device__ __forceinline__ u64t fma2(u64t a, u64t b, u64t c) {
    u64t d; asm("fma.rn.f32x2 %0,%1,%2,%3;" : "=l"(d) : "l"(a), "l"(b), "l"(c)); return d;
}
__device__ __forceinline__ void upk2(u64t v, float& lo, float& hi) {
    asm("mov.b64 {%0,%1},%2;" : "=f"(lo), "=f"(hi) : "l"(v));
}

// ---------------- mma.sync helper (m16n8k16 bf16 -> f32) ----------------
__device__ __forceinline__ void mma16816(float* d, const uint32_t* a, const uint32_t* b) {
    asm volatile(
        "mma.sync.aligned.m16n8k16.row.col.f32.bf16.bf16.f32 "
        "{%0,%1,%2,%3},{%4,%5,%6,%7},{%8,%9},{%0,%1,%2,%3};"
        : "+f"(d[0]), "+f"(d[1]), "+f"(d[2]), "+f"(d[3])
        : "r"(a[0]), "r"(a[1]), "r"(a[2]), "r"(a[3]), "r"(b[0]), "r"(b[1]));
}
__device__ __forceinline__ void tpack(uint2 r0, uint2 r1, uint32_t* w) {
    w[0] = (r0.x & 0xffffu) | (r1.x << 16);
    w[1] = (r0.x >> 16)     | (r1.x & 0xffff0000u);
    w[2] = (r0.y & 0xffffu) | (r1.y << 16);
    w[3] = (r0.y >> 16)     | (r1.y & 0xffff0000u);
}

// ---------------- scratch ----------------
__device__ float g_xc[(size_t)BB * 512 * NP];
__device__ float g_y [(size_t)BB * 256 * NP];
__device__ float g_z [(size_t)BB * 256 * NP];
__device__ float g_sq[BB * NP];
__device__ int   g_idx[BB * NP * KNN];
__device__ float g_dist[(size_t)CHB * NP * NP];        // 67MB reused slice
__device__ float g_hm[BB * 1024];
__device__ float g_h1[BB * 512];
__device__ float g_h2[BB * 256];
__device__ __nv_bfloat16 g_xhi[(size_t)BB * XROWS * NP];
__device__ __nv_bfloat16 g_xlo[(size_t)BB * XROWS * NP];
__device__ __nv_bfloat16 g_whi[1024 * 512];
__device__ __nv_bfloat16 g_wlo[1024 * 512];

// ---------------- small kernels ----------------

__global__ void zero_k(float* p, int n) {
    int t = blockIdx.x * 256 + threadIdx.x;
    if (t < n) p[t] = 0.f;
}

__global__ void sqnorm_k(const float* __restrict__ x, size_t xbs, int C,
                         float* __restrict__ sq) {
    int t = blockIdx.x * 256 + threadIdx.x;
    if (t >= BB * NP) return;
    int b = t / NP, n = t % NP;
    const float* xp = x + (size_t)b * xbs + n;
    float s = 0.f;
    for (int c = 0; c < C; c++) { float v = xp[(size_t)c * NP]; s = fmaf(v, v, s); }
    sq[t] = s;
}

__global__ void cvtw_k(const float* __restrict__ w,
                       __nv_bfloat16* __restrict__ whi, __nv_bfloat16* __restrict__ wlo) {
    int t = blockIdx.x * 256 + threadIdx.x;
    if (t >= 1024 * 512 / 4) return;
    float4 v = *(const float4*)&w[t * 4];
    float fv[4] = { v.x, v.y, v.z, v.w };
    unsigned short h[4], l[4];
#pragma unroll
    for (int q = 0; q < 4; q++) {
        __nv_bfloat16 bh = __float2bfloat16_rn(fv[q]);
        __nv_bfloat16 bl = __float2bfloat16_rn(fv[q] - __bfloat162float(bh));
        h[q] = *(unsigned short*)&bh;
        l[q] = *(unsigned short*)&bl;
    }
    *(uint2*)&whi[t * 4] = make_uint2((uint32_t)h[0] | ((uint32_t)h[1] << 16),
                                      (uint32_t)h[2] | ((uint32_t)h[3] << 16));
    *(uint2*)&wlo[t * 4] = make_uint2((uint32_t)l[0] | ((uint32_t)l[1] << 16),
                                      (uint32_t)l[2] | ((uint32_t)l[3] << 16));
}

// ---------------- dist: fp32 FFMA2, symmetric 128x128 tiles, chunked batches ----------------
__global__ __launch_bounds__(256) void dist2_k(const float* __restrict__ x, size_t xbs, int C,
                                               const float* __restrict__ sq,
                                               float* __restrict__ dist, int bOff) {
    int zb = blockIdx.z;                       // local slice batch
    int b = bOff + zb;                         // global batch
    int t = blockIdx.x;
    int j = (int)((sqrtf(8.f * t + 1.f) - 1.f) * 0.5f);
    while ((j + 1) * (j + 2) / 2 <= t) j++;
    while (j * (j + 1) / 2 > t) j--;
    int i = t - j * (j + 1) / 2;
    int n0 = i * 128, m0 = j * 128;

    __shared__ float As[16][128];
    __shared__ float Bs[16][128];
    int tid = threadIdx.x, tx = tid & 15, ty = tid >> 4;
    const float* xb = x + (size_t)b * xbs;

    u64t acc2[8][4];
#pragma unroll
    for (int r = 0; r < 8; r++)
#pragma unroll
        for (int c = 0; c < 4; c++) acc2[r][c] = 0ull;

    for (int c0 = 0; c0 < C; c0 += 16) {
#pragma unroll
        for (int q = 0; q < 2; q++) {
            int e = tid + q * 256;
            int rr = e >> 5, c4 = (e & 31) * 4;
            float4 va = make_float4(0.f, 0.f, 0.f, 0.f);
            float4 vb = make_float4(0.f, 0.f, 0.f, 0.f);
            if (c0 + rr < C) {
                va = *(const float4*)&xb[(size_t)(c0 + rr) * NP + n0 + c4];
                vb = *(const float4*)&xb[(size_t)(c0 + rr) * NP + m0 + c4];
            }
            *(float4*)&As[rr][c4] = va;
            *(float4*)&Bs[rr][c4] = vb;
        }
        __syncthreads();
#pragma unroll
        for (int kk = 0; kk < 16; kk++) {
            float a[8];
#pragma unroll
            for (int r = 0; r < 8; r++) a[r] = As[kk][ty * 8 + r];
            u64t bv2[4];
#pragma unroll
            for (int c = 0; c < 4; c++) bv2[c] = *(const u64t*)&Bs[kk][tx * 8 + 2 * c];
#pragma unroll
            for (int r = 0; r < 8; r++) {
                u64t a2 = pk2(a[r], a[r]);
#pragma unroll
                for (int c = 0; c < 4; c++) acc2[r][c] = fma2(a2, bv2[c], acc2[r][c]);
            }
        }
        __syncthreads();
    }

    float acc[8][8];
#pragma unroll
    for (int r = 0; r < 8; r++)
#pragma unroll
        for (int c = 0; c < 4; c++) upk2(acc2[r][c], acc[r][2 * c], acc[r][2 * c + 1]);

    float sn[8], sm[8];
#pragma unroll
    for (int r = 0; r < 8; r++) sn[r] = sq[b * NP + n0 + ty * 8 + r];
#pragma unroll
    for (int c = 0; c < 8; c++) sm[c] = sq[b * NP + m0 + tx * 8 + c];
#pragma unroll
    for (int r = 0; r < 8; r++)
#pragma unroll
        for (int c = 0; c < 8; c++) acc[r][c] = 2.f * acc[r][c] - sn[r] - sm[c];

    float* dbase = dist + (size_t)zb * NP * NP;
#pragma unroll
    for (int r = 0; r < 8; r++) {
        float* p = &dbase[(size_t)(n0 + ty * 8 + r) * NP + m0 + tx * 8];
        *(float4*)p       = *(float4*)&acc[r][0];
        *(float4*)(p + 4) = *(float4*)&acc[r][4];
    }
    if (i != j) {
#pragma unroll
        for (int c = 0; c < 8; c++) {
            float4 lo = make_float4(acc[0][c], acc[1][c], acc[2][c], acc[3][c]);
            float4 hi = make_float4(acc[4][c], acc[5][c], acc[6][c], acc[7][c]);
            float* p = &dbase[(size_t)(m0 + tx * 8 + c) * NP + n0 + ty * 8];
            *(float4*)p       = lo;
            *(float4*)(p + 4) = hi;
        }
    }
}

// ---------------- top-K v4, chunked: local slice rows, global idx ----------------
__global__ __launch_bounds__(256) void topk4_k(const float* __restrict__ dist,
                                               int* __restrict__ idxout, int bOff) {
    int rl = blockIdx.x;                       // local row within slice
    const float* row = dist + (size_t)rl * NP;
    int rg = bOff * NP + rl;                   // global row
    int tid = threadIdx.x;
    float f[8];
    *(float4*)(f)     = *(const float4*)&row[tid * 8];
    *(float4*)(f + 4) = *(const float4*)&row[tid * 8 + 4];
    unsigned u[8];
#pragma unroll
    for (int q = 0; q < 8; q++) {
        unsigned bt = __float_as_uint(f[q]);
        u[q] = (bt & 0x80000000u) ? ~bt : (bt | 0x80000000u);
    }
    __shared__ unsigned hist[256];
    __shared__ int sh_hb, sh_need, sh_slot, sh_ecnt;
    __shared__ u64t ebuf[NP];

    hist[tid] = 0u;
    if (tid == 0) { sh_slot = 0; sh_ecnt = 0; }
    __syncthreads();
#pragma unroll
    for (int q = 0; q < 8; q++) atomicAdd(&hist[u[q] >> 24], 1u);
    __syncthreads();

    int lane = tid & 31, w = tid >> 5;
    if (w == 0) {
        int binbase = 255 - lane * 8;
        int h[8], s = 0;
#pragma unroll
        for (int q = 0; q < 8; q++) { h[q] = (int)hist[binbase - q]; s += h[q]; }
        int pre = s;
#pragma unroll
        for (int off = 1; off < 32; off <<= 1) {
            int o = __shfl_up_sync(0xffffffffu, pre, off);
            if (lane >= off) pre += o;
        }
        int excl = pre - s;
        if (excl < KNN && pre >= KNN) {
            int c = excl, q = 0;
            while (c + h[q] < KNN) { c += h[q]; q++; }
            sh_hb = binbase - q;
            sh_need = KNN - c;
        }
    }
    __syncthreads();

    int hb = sh_hb, base = rg * KNN;
#pragma unroll
    for (int q = 0; q < 8; q++) {
        int hbq = (int)(u[q] >> 24);
        int idxv = tid * 8 + q;
        if (hbq > hb) {
            int s = atomicAdd(&sh_slot, 1);
            idxout[base + s] = idxv;
        } else if (hbq == hb) {
            int e = atomicAdd(&sh_ecnt, 1);
            ebuf[e] = ((u64t)u[q] << 32) | (unsigned)(NP - 1 - idxv);
        }
    }
    __syncthreads();

    if (w == 0) {
        int need = sh_need, ecnt = sh_ecnt, wc = sh_slot;
        for (int it = 0; it < need; it++) {
            u64t best = 0ull;
            for (int q = lane; q < ecnt; q += 32) best = max(best, ebuf[q]);
#pragma unroll
            for (int off = 16; off > 0; off >>= 1) {
                u64t o = __shfl_xor_sync(0xffffffffu, best, off);
                if (o > best) best = o;
            }
            if (lane == 0)
                idxout[base + wc + it] = NP - 1 - (int)(unsigned)(best & 0xffffffffu);
            for (int q = lane; q < ecnt; q += 32)
                if (ebuf[q] == best) ebuf[q] = 0ull;
        }
    }
}

// ---------------- fused y+z GEMM (fp32 FFMA2) ----------------
__global__ __launch_bounds__(256) void mmyz_k(const float* __restrict__ X, size_t xbs, int C,
                                              const float* __restrict__ W, int ldw,
                                              int O, float* __restrict__ y,
                                              float* __restrict__ z) {
    int b = blockIdx.z, o0 = blockIdx.y * 64, n0 = blockIdx.x * 128;
    __shared__ float Wn[16][65];
    __shared__ float Wd[16][65];
    __shared__ float Xs[16][128];
    int tid = threadIdx.x, tx = tid & 15, ty = tid >> 4;
    const float* xb = X + (size_t)b * xbs;

    u64t accy[4][4], accz[4][4];
#pragma unroll
    for (int r = 0; r < 4; r++)
#pragma unroll
        for (int c = 0; c < 4; c++) { accy[r][c] = 0ull; accz[r][c] = 0ull; }

    for (int c0 = 0; c0 < C; c0 += 16) {
#pragma unroll
        for (int q = 0; q < 4; q++) {
            int e = tid + q * 256;
            int kk = e & 15, ol = e >> 4;
            int c = c0 + kk;
            float wn = 0.f, wd = 0.f;
            if (c < C) {
                const float* wr = W + (size_t)(o0 + ol) * ldw;
                wn = wr[c];
                wd = wr[C + c] - wn;
            }
            Wn[kk][ol] = wn;
            Wd[kk][ol] = wd;
        }
#pragma unroll
        for (int q = 0; q < 2; q++) {
            int e = tid + q * 256;
            int rr = e >> 5, c4 = (e & 31) * 4;
            float4 v = make_float4(0.f, 0.f, 0.f, 0.f);
            if (c0 + rr < C) v = *(const float4*)&xb[(size_t)(c0 + rr) * NP + n0 + c4];
            *(float4*)&Xs[rr][c4] = v;
        }
        __syncthreads();
#pragma unroll
        for (int kk = 0; kk < 16; kk++) {
            u64t bv2[4];
#pragma unroll
            for (int c = 0; c < 4; c++) bv2[c] = *(const u64t*)&Xs[kk][tx * 8 + 2 * c];
#pragma unroll
            for (int r = 0; r < 4; r++) {
                float an = Wn[kk][ty * 4 + r];
                float ad = Wd[kk][ty * 4 + r];
                u64t an2 = pk2(an, an);
                u64t ad2 = pk2(ad, ad);
#pragma unroll
                for (int c = 0; c < 4; c++) {
                    accy[r][c] = fma2(an2, bv2[c], accy[r][c]);
                    accz[r][c] = fma2(ad2, bv2[c], accz[r][c]);
                }
            }
        }
        __syncthreads();
    }

#pragma unroll
    for (int r = 0; r < 4; r++) {
        int o = o0 + ty * 4 + r;
        float ay[8], az[8];
#pragma unroll
        for (int c = 0; c < 4; c++) {
            upk2(accy[r][c], ay[2 * c], ay[2 * c + 1]);
            upk2(accz[r][c], az[2 * c], az[2 * c + 1]);
        }
        float* py = &y[((size_t)b * O + o) * NP + n0 + tx * 8];
        float* pz = &z[((size_t)b * O + o) * NP + n0 + tx * 8];
        *(float4*)py       = *(float4*)&ay[0];
        *(float4*)(py + 4) = *(float4*)&ay[4];
        *(float4*)pz       = *(float4*)&az[0];
        *(float4*)(pz + 4) = *(float4*)&az[4];
    }
}

// ---------------- conv5 via mma, pre-converted bf16 operands (3-pass hi/lo) ----------------
__global__ __launch_bounds__(256) void conv5_mma_k(const __nv_bfloat16* __restrict__ xhi,
                                                   const __nv_bfloat16* __restrict__ xlo,
                                                   const __nv_bfloat16* __restrict__ whi,
                                                   const __nv_bfloat16* __restrict__ wlo,
                                                   const float* __restrict__ g,
                                                   const float* __restrict__ bb,
                                                   float* __restrict__ out) {
    __shared__ __nv_bfloat16 Ahi[128 * ASTR];
    __shared__ __nv_bfloat16 Alo[128 * ASTR];
    __shared__ __nv_bfloat16 Bhi[128 * ASTR];
    __shared__ __nv_bfloat16 Blo[128 * ASTR];

    int b = blockIdx.z, o0 = blockIdx.y * 128, n0 = blockIdx.x * 128;
    int tid = threadIdx.x, lane = tid & 31, wid = tid >> 5;
    int wm = wid >> 2, wn = wid & 3;
    const __nv_bfloat16* xh = xhi + (size_t)b * XROWS * NP;
    const __nv_bfloat16* xl = xlo + (size_t)b * XROWS * NP;

    float acc[4][4][4];
#pragma unroll
    for (int mf = 0; mf < 4; mf++)
#pragma unroll
        for (int nf = 0; nf < 4; nf++)
#pragma unroll
            for (int q = 0; q < 4; q++) acc[mf][nf][q] = 0.f;

    for (int c0 = 0; c0 < 512; c0 += 32) {
#pragma unroll
        for (int it = 0; it < 2; it++) {
            int e = tid + it * 256;
            int row = e >> 2, k8 = (e & 3) * 8;
            *(uint4*)&Ahi[row * ASTR + k8] = *(const uint4*)&whi[(size_t)(o0 + row) * 512 + c0 + k8];
            *(uint4*)&Alo[row * ASTR + k8] = *(const uint4*)&wlo[(size_t)(o0 + row) * 512 + c0 + k8];
        }
#pragma unroll
        for (int it = 0; it < 2; it++) {
            int e = tid + it * 256;
            int kp = e & 15, n4 = (e >> 4) * 4;
            int c = c0 + 2 * kp;
            uint2 bh  = *(const uint2*)&xh[(size_t)c * NP + n0 + n4];
            uint2 bl  = *(const uint2*)&xl[(size_t)c * NP + n0 + n4];
            uint2 b1h = *(const uint2*)&xh[(size_t)(c + 1) * NP + n0 + n4];
            uint2 b1l = *(const uint2*)&xl[(size_t)(c + 1) * NP + n0 + n4];
            uint32_t wb[4], wbl[4];
            tpack(bh, b1h, wb);
            tpack(bl, b1l, wbl);
#pragma unroll
            for (int q = 0; q < 4; q++) {
                *(uint32_t*)&Bhi[(n4 + q) * ASTR + 2 * kp] = wb[q];
                *(uint32_t*)&Blo[(n4 + q) * ASTR + 2 * kp] = wbl[q];
            }
        }
        __syncthreads();

        int r0 = lane >> 2, cq = (lane & 3) * 2;
#pragma unroll
        for (int ks = 0; ks < 2; ks++) {
            int kb = ks * 16;
            uint32_t ah[4][4], al[4][4], bh[4][2], bl[4][2];
#pragma unroll
            for (int mf = 0; mf < 4; mf++) {
                int am = wm * 64 + mf * 16;
                ah[mf][0] = *(uint32_t*)&Ahi[(am + r0) * ASTR + kb + cq];
                ah[mf][1] = *(uint32_t*)&Ahi[(am + r0 + 8) * ASTR + kb + cq];
                ah[mf][2] = *(uint32_t*)&Ahi[(am + r0) * ASTR + kb + cq + 8];
                ah[mf][3] = *(uint32_t*)&Ahi[(am + r0 + 8) * ASTR + kb + cq + 8];
                al[mf][0] = *(uint32_t*)&Alo[(am + r0) * ASTR + kb + cq];
                al[mf][1] = *(uint32_t*)&Alo[(am + r0 + 8) * ASTR + kb + cq];
                al[mf][2] = *(uint32_t*)&Alo[(am + r0) * ASTR + kb + cq + 8];
                al[mf][3] = *(uint32_t*)&Alo[(am + r0 + 8) * ASTR + kb + cq + 8];
            }
#pragma unroll
            for (int nf = 0; nf < 4; nf++) {
                int bn = wn * 32 + nf * 8;
                bh[nf][0] = *(uint32_t*)&Bhi[(bn + r0) * ASTR + kb + cq];
                bh[nf][1] = *(uint32_t*)&Bhi[(bn + r0) * ASTR + kb + cq + 8];
                bl[nf][0] = *(uint32_t*)&Blo[(bn + r0) * ASTR + kb + cq];
                bl[nf][1] = *(uint32_t*)&Blo[(bn + r0) * ASTR + kb + cq + 8];
            }
#pragma unroll
            for (int mf = 0; mf < 4; mf++)
#pragma unroll
                for (int nf = 0; nf < 4; nf++) {
                    mma16816(acc[mf][nf], ah[mf], bh[nf]);
                    mma16816(acc[mf][nf], ah[mf], bl[nf]);
                    mma16816(acc[mf][nf], al[mf], bh[nf]);
                }
        }
        __syncthreads();
    }

    float rs = rsqrtf(1.f + 1e-5f);
#pragma unroll
    for (int mf = 0; mf < 4; mf++) {
        int o_r = o0 + wm * 64 + mf * 16 + (lane >> 2);
        float gn0 = g[o_r] * rs,     bo0 = bb[o_r];
        float gn1 = g[o_r + 8] * rs, bo1 = bb[o_r + 8];
        float m0 = 0.f, m1 = 0.f;
#pragma unroll
        for (int nf = 0; nf < 4; nf++) {
            m0 = fmaxf(m0, fmaxf(fmaf(gn0, acc[mf][nf][0], bo0), fmaf(gn0, acc[mf][nf][1], bo0)));
            m1 = fmaxf(m1, fmaxf(fmaf(gn1, acc[mf][nf][2], bo1), fmaf(gn1, acc[mf][nf][3], bo1)));
        }
        m0 = fmaxf(m0, 0.f); m1 = fmaxf(m1, 0.f);
#pragma unroll
        for (int off = 1; off <= 2; off <<= 1) {
            m0 = fmaxf(m0, __shfl_xor_sync(0xffffffffu, m0, off));
            m1 = fmaxf(m1, __shfl_xor_sync(0xffffffffu, m1, off));
        }
        if ((lane & 3) == 0) {
            atomicMax((int*)out + (size_t)b * 1024 + o_r,     __float_as_int(m0));
            atomicMax((int*)out + (size_t)b * 1024 + o_r + 8, __float_as_int(m1));
        }
    }
}

// ---------------- gather + max_k + bn + relu + fused bf16 hi/lo emit ----------------
__global__ __launch_bounds__(256) void gathermax_k(const float* __restrict__ y,
                                                   const float* __restrict__ z,
                                                   const int* __restrict__ idx,
                                                   const float* __restrict__ g,
                                                   const float* __restrict__ bb,
                                                   int O, float* __restrict__ out, size_t obs,
                                                   __nv_bfloat16* __restrict__ xhi,
                                                   __nv_bfloat16* __restrict__ xlo,
                                                   int outRow) {
    int b = blockIdx.z, n0 = blockIdx.y * 64, o0 = blockIdx.x * 4;
    __shared__ int sidx[64 * KNN];
    for (int e = threadIdx.x; e < 64 * KNN; e += 256) {
        int nl = e / KNN, kk = e % KNN;
        sidx[e] = idx[((size_t)(b * NP + n0 + nl)) * KNN + kk];
    }
    __syncthreads();
    int nl = threadIdx.x & 63, ol = threadIdx.x >> 6;
    int o = o0 + ol, n = n0 + nl;
    const float* yp = y + ((size_t)b * O + o) * NP;
    float m = NEG_INF;
#pragma unroll
    for (int kk = 0; kk < KNN; kk++) m = fmaxf(m, yp[sidx[nl * KNN + kk]]);
    float v = m + z[((size_t)b * O + o) * NP + n];
    float rs = rsqrtf(1.f + 1e-5f);
    v = fmaxf(fmaf(g[o] * rs, v, bb[o]), 0.f);
    out[(size_t)b * obs + (size_t)o * NP + n] = v;
    __nv_bfloat16 bh = __float2bfloat16_rn(v);
    __nv_bfloat16 bl = __float2bfloat16_rn(v - __bfloat162float(bh));
    size_t o2 = ((size_t)b * XROWS + outRow + o) * NP + n;
    xhi[o2] = bh;
    xlo[o2] = bl;
}

// ---------------- FC head ----------------
__global__ void fc_k(const float* __restrict__ in, int CI, const float* __restrict__ W,
                     int CO, const float* __restrict__ g, const float* __restrict__ bb,
                     float* __restrict__ out, int act) {
    int t = blockIdx.x * 256 + threadIdx.x;
    if (t >= BB * CO) return;
    int b = t / CO, j = t % CO;
    const float4* ip = (const float4*)(in + (size_t)b * CI);
    const float4* wp = (const float4*)(W + (size_t)j * CI);
    float s = 0.f;
    for (int c = 0; c < CI / 4; c++) {
        float4 a = ip[c], w = wp[c];
        s = fmaf(a.x, w.x, s); s = fmaf(a.y, w.y, s);
        s = fmaf(a.z, w.z, s); s = fmaf(a.w, w.w, s);
    }
    if (act) {
        float rs = rsqrtf(1.f + 1e-5f);
        s = fmaxf(fmaf(g[j] * rs, s, bb[j]), 0.f);
    }
    out[t] = s;
}

// ---------------- host side ----------------

static cudaStream_t s1 = nullptr;
static cudaEvent_t evF[4], evM[4];

static void edge_conv_launch(int li, const float* xin, size_t xbs, int C,
                             const float* W, int ldw, int O, int outRow,
                             const float* g, const float* bbp,
                             float* xc, float* y, float* z, float* sq, float* dist,
                             int* idxp, __nv_bfloat16* xhi, __nv_bfloat16* xlo) {
    // fork: mmyz (independent of dist/topk chain) on side stream
    cudaEventRecord(evF[li], 0);
    cudaStreamWaitEvent(s1, evF[li], 0);
    mmyz_k<<<dim3(NP / 128, O / 64, BB), 256, 0, s1>>>(xin, xbs, C, W, ldw, O, y, z);
    cudaEventRecord(evM[li], s1);

    // main chain: chunked dist->topk so topk reads hit L2
    sqnorm_k<<<(BB * NP + 255) / 256, 256>>>(xin, xbs, C, sq);
    for (int ch = 0; ch < BB / CHB; ch++) {
        int bOff = ch * CHB;
        dist2_k<<<dim3(136, 1, CHB), 256>>>(xin, xbs, C, sq, dist, bOff);
        topk4_k<<<CHB * NP, 256>>>(dist, idxp, bOff);
    }

    // join: gathermax needs idx + y + z
    cudaStreamWaitEvent(0, evM[li], 0);
    gathermax_k<<<dim3(O / 4, NP / 64, BB), 256>>>(y, z, idxp, g, bbp, O,
                                                   xc + (size_t)outRow * NP, (size_t)512 * NP,
                                                   xhi, xlo, outRow);
}

extern "C" void kernel_launch(void* const* d_in, const int* in_sizes, int n_in,
                              void* d_out, int out_size) {
    const float* x   = (const float*)d_in[0];
    const float* w1  = (const float*)d_in[1];
    const float* w2  = (const float*)d_in[2];
    const float* w3  = (const float*)d_in[3];
    const float* w4  = (const float*)d_in[4];
    const float* w5  = (const float*)d_in[5];
    const float* fw1 = (const float*)d_in[6];
    const float* fw2 = (const float*)d_in[7];
    const float* fw3 = (const float*)d_in[8];
    const float* g1 = (const float*)d_in[9],  *b1 = (const float*)d_in[10];
    const float* g2 = (const float*)d_in[11], *b2 = (const float*)d_in[12];
    const float* g3 = (const float*)d_in[13], *b3 = (const float*)d_in[14];
    const float* g4 = (const float*)d_in[15], *b4 = (const float*)d_in[16];
    const float* g5 = (const float*)d_in[17], *b5 = (const float*)d_in[18];
    const float* g6 = (const float*)d_in[19], *b6 = (const float*)d_in[20];
    const float* g7 = (const float*)d_in[21], *b7 = (const float*)d_in[22];

    float *xc, *y, *z, *sq, *dist, *hm, *h1, *h2;
    int* idxp;
    __nv_bfloat16 *xhi, *xlo, *whi, *wlo;
    cudaGetSymbolAddress((void**)&xc,   g_xc);
    cudaGetSymbolAddress((void**)&y,    g_y);
    cudaGetSymbolAddress((void**)&z,    g_z);
    cudaGetSymbolAddress((void**)&sq,   g_sq);
    cudaGetSymbolAddress((void**)&dist, g_dist);
    cudaGetSymbolAddress((void**)&hm,   g_hm);
    cudaGetSymbolAddress((void**)&h1,   g_h1);
    cudaGetSymbolAddress((void**)&h2,   g_h2);
    cudaGetSymbolAddress((void**)&idxp, g_idx);
    cudaGetSymbolAddress((void**)&xhi,  g_xhi);
    cudaGetSymbolAddress((void**)&xlo,  g_xlo);
    cudaGetSymbolAddress((void**)&whi,  g_whi);
    cudaGetSymbolAddress((void**)&wlo,  g_wlo);

    if (!s1) {
        cudaStreamCreateWithFlags(&s1, cudaStreamNonBlocking);
        for (int i = 0; i < 4; i++) {
            cudaEventCreateWithFlags(&evF[i], cudaEventDisableTiming);
            cudaEventCreateWithFlags(&evM[i], cudaEventDisableTiming);
        }
    }

    zero_k<<<(BB * 1024 + 255) / 256, 256>>>(hm, BB * 1024);
    cvtw_k<<<(1024 * 512 / 4 + 255) / 256, 256>>>(w5, whi, wlo);

    edge_conv_launch(0, x,                     (size_t)3 * NP,   3,   w1, 6,   64,  0,
                     g1, b1, xc, y, z, sq, dist, idxp, xhi, xlo);
    edge_conv_launch(1, xc,                    (size_t)512 * NP, 64,  w2, 128, 64,  64,
                     g2, b2, xc, y, z, sq, dist, idxp, xhi, xlo);
    edge_conv_launch(2, xc + (size_t)64 * NP,  (size_t)512 * NP, 64,  w3, 128, 128, 128,
                     g3, b3, xc, y, z, sq, dist, idxp, xhi, xlo);
    edge_conv_launch(3, xc + (size_t)128 * NP, (size_t)512 * NP, 128, w4, 256, 256, 256,
                     g4, b4, xc, y, z, sq, dist, idxp, xhi, xlo);

    conv5_mma_k<<<dim3(NP / 128, 1024 / 128, BB), 256>>>(xhi, xlo, whi, wlo, g5, b5, hm);

    fc_k<<<(BB * 512 + 255) / 256, 256>>>(hm, 1024, fw1, 512, g6, b6, h1, 1);
    fc_k<<<(BB * 256 + 255) / 256, 256>>>(h1, 512, fw2, 256, g7, b7, h2, 1);
    fc_k<<<(BB * 40 + 255) / 256, 256>>>(h2, 256, fw3, 40, nullptr, nullptr, (float*)d_out, 0);
}

// round 15
// speedup vs baseline: 1.6687x; 1.6687x over previous
#include <cuda_runtime.h>
#include <cuda_bf16.h>
#include <cstdint>
#include <cstdio>

#define BB  8
#define NP  2048
#define KNN 20
#define NEG_INF (-3.4e38f)
#define ASTR 40
#define XROWS 512
#define CCAP 256

typedef unsigned long long u64t;

// ---------------- f32x2 packed-FMA helpers ----------------
__device__ __forceinline__ u64t pk2(float lo, float hi) {
    u64t d; asm("mov.b64 %0,{%1,%2};" : "=l"(d) : "f"(lo), "f"(hi)); return d;
}
__device__ __forceinline__ u64t fma2(u64t a, u64t b, u64t c) {
    u64t d; asm("fma.rn.f32x2 %0,%1,%2,%3;" : "=l"(d) : "l"(a), "l"(b), "l"(c)); return d;
}
__device__ __forceinline__ void upk2(u64t v, float& lo, float& hi) {
    asm("mov.b64 {%0,%1},%2;" : "=f"(lo), "=f"(hi) : "l"(v));
}

// ---------------- mma.sync helper (m16n8k16 bf16 -> f32) ----------------
__device__ __forceinline__ void mma16816(float* d, const uint32_t* a, const uint32_t* b) {
    asm volatile(
        "mma.sync.aligned.m16n8k16.row.col.f32.bf16.bf16.f32 "
        "{%0,%1,%2,%3},{%4,%5,%6,%7},{%8,%9},{%0,%1,%2,%3};"
        : "+f"(d[0]), "+f"(d[1]), "+f"(d[2]), "+f"(d[3])
        : "r"(a[0]), "r"(a[1]), "r"(a[2]), "r"(a[3]), "r"(b[0]), "r"(b[1]));
}
__device__ __forceinline__ void tpack(uint2 r0, uint2 r1, uint32_t* w) {
    w[0] = (r0.x & 0xffffu) | (r1.x << 16);
    w[1] = (r0.x >> 16)     | (r1.x & 0xffff0000u);
    w[2] = (r0.y & 0xffffu) | (r1.y << 16);
    w[3] = (r0.y >> 16)     | (r1.y & 0xffff0000u);
}
__device__ __forceinline__ unsigned monomap(float x) {
    unsigned bt = __float_as_uint(x);
    return (bt & 0x80000000u) ? ~bt : (bt | 0x80000000u);
}

// ---------------- scratch ----------------
__device__ float g_xc[(size_t)BB * 512 * NP];
__device__ float g_y [(size_t)BB * 256 * NP];
__device__ float g_z [(size_t)BB * 256 * NP];
__device__ float g_sq[BB * NP];
__device__ int   g_idx[BB * NP * KNN];
__device__ float g_dist[(size_t)BB * NP * NP];
__device__ u64t  g_cand[(size_t)BB * NP * CCAP];
__device__ unsigned g_meta[BB * NP];
__device__ float g_hm[BB * 1024];
__device__ float g_h1[BB * 512];
__device__ float g_h2[BB * 256];
__device__ __nv_bfloat16 g_xhi[(size_t)BB * XROWS * NP];
__device__ __nv_bfloat16 g_xlo[(size_t)BB * XROWS * NP];
__device__ __nv_bfloat16 g_whi[1024 * 512];
__device__ __nv_bfloat16 g_wlo[1024 * 512];

// ---------------- small kernels ----------------

__global__ void zero_k(float* p, int n) {
    int t = blockIdx.x * 256 + threadIdx.x;
    if (t < n) p[t] = 0.f;
}

__global__ void sqnorm_k(const float* __restrict__ x, size_t xbs, int C,
                         float* __restrict__ sq) {
    int t = blockIdx.x * 256 + threadIdx.x;
    if (t >= BB * NP) return;
    int b = t / NP, n = t % NP;
    const float* xp = x + (size_t)b * xbs + n;
    float s = 0.f;
    for (int c = 0; c < C; c++) { float v = xp[(size_t)c * NP]; s = fmaf(v, v, s); }
    sq[t] = s;
}

__global__ void cvtw_k(const float* __restrict__ w,
                       __nv_bfloat16* __restrict__ whi, __nv_bfloat16* __restrict__ wlo) {
    int t = blockIdx.x * 256 + threadIdx.x;
    if (t >= 1024 * 512 / 4) return;
    float4 v = *(const float4*)&w[t * 4];
    float fv[4] = { v.x, v.y, v.z, v.w };
    unsigned short h[4], l[4];
#pragma unroll
    for (int q = 0; q < 4; q++) {
        __nv_bfloat16 bh = __float2bfloat16_rn(fv[q]);
        __nv_bfloat16 bl = __float2bfloat16_rn(fv[q] - __bfloat162float(bh));
        h[q] = *(unsigned short*)&bh;
        l[q] = *(unsigned short*)&bl;
    }
    *(uint2*)&whi[t * 4] = make_uint2((uint32_t)h[0] | ((uint32_t)h[1] << 16),
                                      (uint32_t)h[2] | ((uint32_t)h[3] << 16));
    *(uint2*)&wlo[t * 4] = make_uint2((uint32_t)l[0] | ((uint32_t)l[1] << 16),
                                      (uint32_t)l[2] | ((uint32_t)l[3] << 16));
}

// ---------------- dist: fp32 FFMA2, symmetric 128x128 tiles (proven) ----------------
__global__ __launch_bounds__(256) void dist2_k(const float* __restrict__ x, size_t xbs, int C,
                                               const float* __restrict__ sq,
                                               float* __restrict__ dist) {
    int b = blockIdx.z;
    int t = blockIdx.x;
    int j = (int)((sqrtf(8.f * t + 1.f) - 1.f) * 0.5f);
    while ((j + 1) * (j + 2) / 2 <= t) j++;
    while (j * (j + 1) / 2 > t) j--;
    int i = t - j * (j + 1) / 2;
    int n0 = i * 128, m0 = j * 128;

    __shared__ float As[16][128];
    __shared__ float Bs[16][128];
    int tid = threadIdx.x, tx = tid & 15, ty = tid >> 4;
    const float* xb = x + (size_t)b * xbs;

    u64t acc2[8][4];
#pragma unroll
    for (int r = 0; r < 8; r++)
#pragma unroll
        for (int c = 0; c < 4; c++) acc2[r][c] = 0ull;

    for (int c0 = 0; c0 < C; c0 += 16) {
#pragma unroll
        for (int q = 0; q < 2; q++) {
            int e = tid + q * 256;
            int rr = e >> 5, c4 = (e & 31) * 4;
            float4 va = make_float4(0.f, 0.f, 0.f, 0.f);
            float4 vb = make_float4(0.f, 0.f, 0.f, 0.f);
            if (c0 + rr < C) {
                va = *(const float4*)&xb[(size_t)(c0 + rr) * NP + n0 + c4];
                vb = *(const float4*)&xb[(size_t)(c0 + rr) * NP + m0 + c4];
            }
            *(float4*)&As[rr][c4] = va;
            *(float4*)&Bs[rr][c4] = vb;
        }
        __syncthreads();
#pragma unroll
        for (int kk = 0; kk < 16; kk++) {
            float a[8];
#pragma unroll
            for (int r = 0; r < 8; r++) a[r] = As[kk][ty * 8 + r];
            u64t bv2[4];
#pragma unroll
            for (int c = 0; c < 4; c++) bv2[c] = *(const u64t*)&Bs[kk][tx * 8 + 2 * c];
#pragma unroll
            for (int r = 0; r < 8; r++) {
                u64t a2 = pk2(a[r], a[r]);
#pragma unroll
                for (int c = 0; c < 4; c++) acc2[r][c] = fma2(a2, bv2[c], acc2[r][c]);
            }
        }
        __syncthreads();
    }

    float acc[8][8];
#pragma unroll
    for (int r = 0; r < 8; r++)
#pragma unroll
        for (int c = 0; c < 4; c++) upk2(acc2[r][c], acc[r][2 * c], acc[r][2 * c + 1]);

    float sn[8], sm[8];
#pragma unroll
    for (int r = 0; r < 8; r++) sn[r] = sq[b * NP + n0 + ty * 8 + r];
#pragma unroll
    for (int c = 0; c < 8; c++) sm[c] = sq[b * NP + m0 + tx * 8 + c];
#pragma unroll
    for (int r = 0; r < 8; r++)
#pragma unroll
        for (int c = 0; c < 8; c++) acc[r][c] = 2.f * acc[r][c] - sn[r] - sm[c];

    float* dbase = dist + (size_t)b * NP * NP;
#pragma unroll
    for (int r = 0; r < 8; r++) {
        float* p = &dbase[(size_t)(n0 + ty * 8 + r) * NP + m0 + tx * 8];
        *(float4*)p       = *(float4*)&acc[r][0];
        *(float4*)(p + 4) = *(float4*)&acc[r][4];
    }
    if (i != j) {
#pragma unroll
        for (int c = 0; c < 8; c++) {
            float4 lo = make_float4(acc[0][c], acc[1][c], acc[2][c], acc[3][c]);
            float4 hi = make_float4(acc[4][c], acc[5][c], acc[6][c], acc[7][c]);
            float* p = &dbase[(size_t)(m0 + tx * 8 + c) * NP + n0 + ty * 8];
            *(float4*)p       = lo;
            *(float4*)(p + 4) = hi;
        }
    }
}

// ---------------- topk phase A: histogram + threshold + winners + candidates ----------------
__global__ __launch_bounds__(256) void topkA_k(const float* __restrict__ dist,
                                               int* __restrict__ idxout,
                                               u64t* __restrict__ cand,
                                               unsigned* __restrict__ meta) {
    int r = blockIdx.x;
    const float* row = dist + (size_t)r * NP;
    int tid = threadIdx.x;
    float f[8];
    *(float4*)(f)     = *(const float4*)&row[tid * 8];
    *(float4*)(f + 4) = *(const float4*)&row[tid * 8 + 4];
    unsigned u[8];
#pragma unroll
    for (int q = 0; q < 8; q++) u[q] = monomap(f[q]);

    __shared__ unsigned hist[256];
    __shared__ int sh_hb, sh_need, sh_slot, sh_ecnt;
    hist[tid] = 0u;
    if (tid == 0) { sh_slot = 0; sh_ecnt = 0; }
    __syncthreads();
#pragma unroll
    for (int q = 0; q < 8; q++) atomicAdd(&hist[u[q] >> 24], 1u);
    __syncthreads();

    int lane = tid & 31, w = tid >> 5;
    if (w == 0) {
        int binbase = 255 - lane * 8;
        int h[8], s = 0;
#pragma unroll
        for (int q = 0; q < 8; q++) { h[q] = (int)hist[binbase - q]; s += h[q]; }
        int pre = s;
#pragma unroll
        for (int off = 1; off < 32; off <<= 1) {
            int o = __shfl_up_sync(0xffffffffu, pre, off);
            if (lane >= off) pre += o;
        }
        int excl = pre - s;
        if (excl < KNN && pre >= KNN) {
            int c = excl, q = 0;
            while (c + h[q] < KNN) { c += h[q]; q++; }
            sh_hb = binbase - q;
            sh_need = KNN - c;
        }
    }
    __syncthreads();

    int hb = sh_hb, base = r * KNN;
#pragma unroll
    for (int q = 0; q < 8; q++) {
        int hbq = (int)(u[q] >> 24);
        int idxv = tid * 8 + q;
        if (hbq > hb) {
            int s = atomicAdd(&sh_slot, 1);
            idxout[base + s] = idxv;
        } else if (hbq == hb) {
            int e = atomicAdd(&sh_ecnt, 1);
            if (e < CCAP)
                cand[(size_t)r * CCAP + e] = ((u64t)u[q] << 32) | (unsigned)(NP - 1 - idxv);
        }
    }
    __syncthreads();
    if (tid == 0)
        meta[r] = ((unsigned)hb << 24) | ((unsigned)sh_need << 16) | (unsigned)sh_ecnt;
}

// ---------------- topk phase B: one warp per row, pop 'need' from candidates ----------------
__global__ __launch_bounds__(256) void topkB_k(const float* __restrict__ dist,
                                               const u64t* __restrict__ cand,
                                               const unsigned* __restrict__ meta,
                                               int* __restrict__ idxout) {
    int r = blockIdx.x * 8 + (threadIdx.x >> 5);
    int lane = threadIdx.x & 31;
    unsigned mt = meta[r];
    int hb = (int)(mt >> 24);
    int need = (int)((mt >> 16) & 0xffu);
    int ecnt = (int)(mt & 0xffffu);
    int wc = KNN - need;
    int base = r * KNN;

    if (ecnt <= CCAP) {
        const u64t* cp = cand + (size_t)r * CCAP;
        // local copy in registers (ecnt <= 256 -> up to 8 per lane)
        u64t v[8];
#pragma unroll
        for (int q = 0; q < 8; q++) {
            int i = lane + q * 32;
            v[q] = (i < ecnt) ? cp[i] : 0ull;
        }
        for (int it = 0; it < need; it++) {
            u64t best = 0ull;
#pragma unroll
            for (int q = 0; q < 8; q++) best = max(best, v[q]);
#pragma unroll
            for (int off = 16; off > 0; off >>= 1) {
                u64t o = __shfl_xor_sync(0xffffffffu, best, off);
                if (o > best) best = o;
            }
            if (lane == 0)
                idxout[base + wc + it] = NP - 1 - (int)(unsigned)(best & 0xffffffffu);
#pragma unroll
            for (int q = 0; q < 8; q++) if (v[q] == best) v[q] = 0ull;
        }
    } else {
        // rare fallback: strictly-decreasing-key rescan of the dist row
        const float* row = dist + (size_t)r * NP;
        u64t prev = ~0ull;
        for (int it = 0; it < need; it++) {
            u64t best = 0ull;
            for (int i = lane; i < NP; i += 32) {
                unsigned uu = monomap(row[i]);
                if ((int)(uu >> 24) == hb) {
                    u64t key = ((u64t)uu << 32) | (unsigned)(NP - 1 - i);
                    if (key < prev && key > best) best = key;
                }
            }
#pragma unroll
            for (int off = 16; off > 0; off >>= 1) {
                u64t o = __shfl_xor_sync(0xffffffffu, best, off);
                if (o > best) best = o;
            }
            prev = best;
            if (lane == 0)
                idxout[base + wc + it] = NP - 1 - (int)(unsigned)(best & 0xffffffffu);
        }
    }
}

// ---------------- fused y+z GEMM (fp32 FFMA2) ----------------
__global__ __launch_bounds__(256) void mmyz_k(const float* __restrict__ X, size_t xbs, int C,
                                              const float* __restrict__ W, int ldw,
                                              int O, float* __restrict__ y,
                                              float* __restrict__ z) {
    int b = blockIdx.z, o0 = blockIdx.y * 64, n0 = blockIdx.x * 128;
    __shared__ float Wn[16][65];
    __shared__ float Wd[16][65];
    __shared__ float Xs[16][128];
    int tid = threadIdx.x, tx = tid & 15, ty = tid >> 4;
    const float* xb = X + (size_t)b * xbs;

    u64t accy[4][4], accz[4][4];
#pragma unroll
    for (int r = 0; r < 4; r++)
#pragma unroll
        for (int c = 0; c < 4; c++) { accy[r][c] = 0ull; accz[r][c] = 0ull; }

    for (int c0 = 0; c0 < C; c0 += 16) {
#pragma unroll
        for (int q = 0; q < 4; q++) {
            int e = tid + q * 256;
            int kk = e & 15, ol = e >> 4;
            int c = c0 + kk;
            float wn = 0.f, wd = 0.f;
            if (c < C) {
                const float* wr = W + (size_t)(o0 + ol) * ldw;
                wn = wr[c];
                wd = wr[C + c] - wn;
            }
            Wn[kk][ol] = wn;
            Wd[kk][ol] = wd;
        }
#pragma unroll
        for (int q = 0; q < 2; q++) {
            int e = tid + q * 256;
            int rr = e >> 5, c4 = (e & 31) * 4;
            float4 v = make_float4(0.f, 0.f, 0.f, 0.f);
            if (c0 + rr < C) v = *(const float4*)&xb[(size_t)(c0 + rr) * NP + n0 + c4];
            *(float4*)&Xs[rr][c4] = v;
        }
        __syncthreads();
#pragma unroll
        for (int kk = 0; kk < 16; kk++) {
            u64t bv2[4];
#pragma unroll
            for (int c = 0; c < 4; c++) bv2[c] = *(const u64t*)&Xs[kk][tx * 8 + 2 * c];
#pragma unroll
            for (int r = 0; r < 4; r++) {
                float an = Wn[kk][ty * 4 + r];
                float ad = Wd[kk][ty * 4 + r];
                u64t an2 = pk2(an, an);
                u64t ad2 = pk2(ad, ad);
#pragma unroll
                for (int c = 0; c < 4; c++) {
                    accy[r][c] = fma2(an2, bv2[c], accy[r][c]);
                    accz[r][c] = fma2(ad2, bv2[c], accz[r][c]);
                }
            }
        }
        __syncthreads();
    }

#pragma unroll
    for (int r = 0; r < 4; r++) {
        int o = o0 + ty * 4 + r;
        float ay[8], az[8];
#pragma unroll
        for (int c = 0; c < 4; c++) {
            upk2(accy[r][c], ay[2 * c], ay[2 * c + 1]);
            upk2(accz[r][c], az[2 * c], az[2 * c + 1]);
        }
        float* py = &y[((size_t)b * O + o) * NP + n0 + tx * 8];
        float* pz = &z[((size_t)b * O + o) * NP + n0 + tx * 8];
        *(float4*)py       = *(float4*)&ay[0];
        *(float4*)(py + 4) = *(float4*)&ay[4];
        *(float4*)pz       = *(float4*)&az[0];
        *(float4*)(pz + 4) = *(float4*)&az[4];
    }
}

// ---------------- conv5 via mma, pre-converted bf16 operands (3-pass hi/lo) ----------------
__global__ __launch_bounds__(256) void conv5_mma_k(const __nv_bfloat16* __restrict__ xhi,
                                                   const __nv_bfloat16* __restrict__ xlo,
                                                   const __nv_bfloat16* __restrict__ whi,
                                                   const __nv_bfloat16* __restrict__ wlo,
                                                   const float* __restrict__ g,
                                                   const float* __restrict__ bb,
                                                   float* __restrict__ out) {
    __shared__ __nv_bfloat16 Ahi[128 * ASTR];
    __shared__ __nv_bfloat16 Alo[128 * ASTR];
    __shared__ __nv_bfloat16 Bhi[128 * ASTR];
    __shared__ __nv_bfloat16 Blo[128 * ASTR];

    int b = blockIdx.z, o0 = blockIdx.y * 128, n0 = blockIdx.x * 128;
    int tid = threadIdx.x, lane = tid & 31, wid = tid >> 5;
    int wm = wid >> 2, wn = wid & 3;
    const __nv_bfloat16* xh = xhi + (size_t)b * XROWS * NP;
    const __nv_bfloat16* xl = xlo + (size_t)b * XROWS * NP;

    float acc[4][4][4];
#pragma unroll
    for (int mf = 0; mf < 4; mf++)
#pragma unroll
        for (int nf = 0; nf < 4; nf++)
#pragma unroll
            for (int q = 0; q < 4; q++) acc[mf][nf][q] = 0.f;

    for (int c0 = 0; c0 < 512; c0 += 32) {
#pragma unroll
        for (int it = 0; it < 2; it++) {
            int e = tid + it * 256;
            int row = e >> 2, k8 = (e & 3) * 8;
            *(uint4*)&Ahi[row * ASTR + k8] = *(const uint4*)&whi[(size_t)(o0 + row) * 512 + c0 + k8];
            *(uint4*)&Alo[row * ASTR + k8] = *(const uint4*)&wlo[(size_t)(o0 + row) * 512 + c0 + k8];
        }
#pragma unroll
        for (int it = 0; it < 2; it++) {
            int e = tid + it * 256;
            int kp = e & 15, n4 = (e >> 4) * 4;
            int c = c0 + 2 * kp;
            uint2 bh  = *(const uint2*)&xh[(size_t)c * NP + n0 + n4];
            uint2 bl  = *(const uint2*)&xl[(size_t)c * NP + n0 + n4];
            uint2 b1h = *(const uint2*)&xh[(size_t)(c + 1) * NP + n0 + n4];
            uint2 b1l = *(const uint2*)&xl[(size_t)(c + 1) * NP + n0 + n4];
            uint32_t wb[4], wbl[4];
            tpack(bh, b1h, wb);
            tpack(bl, b1l, wbl);
#pragma unroll
            for (int q = 0; q < 4; q++) {
                *(uint32_t*)&Bhi[(n4 + q) * ASTR + 2 * kp] = wb[q];
                *(uint32_t*)&Blo[(n4 + q) * ASTR + 2 * kp] = wbl[q];
            }
        }
        __syncthreads();

        int r0 = lane >> 2, cq = (lane & 3) * 2;
#pragma unroll
        for (int ks = 0; ks < 2; ks++) {
            int kb = ks * 16;
            uint32_t ah[4][4], al[4][4], bh[4][2], bl[4][2];
#pragma unroll
            for (int mf = 0; mf < 4; mf++) {
                int am = wm * 64 + mf * 16;
                ah[mf][0] = *(uint32_t*)&Ahi[(am + r0) * ASTR + kb + cq];
                ah[mf][1] = *(uint32_t*)&Ahi[(am + r0 + 8) * ASTR + kb + cq];
                ah[mf][2] = *(uint32_t*)&Ahi[(am + r0) * ASTR + kb + cq + 8];
                ah[mf][3] = *(uint32_t*)&Ahi[(am + r0 + 8) * ASTR + kb + cq + 8];
                al[mf][0] = *(uint32_t*)&Alo[(am + r0) * ASTR + kb + cq];
                al[mf][1] = *(uint32_t*)&Alo[(am + r0 + 8) * ASTR + kb + cq];
                al[mf][2] = *(uint32_t*)&Alo[(am + r0) * ASTR + kb + cq + 8];
                al[mf][3] = *(uint32_t*)&Alo[(am + r0 + 8) * ASTR + kb + cq + 8];
            }
#pragma unroll
            for (int nf = 0; nf < 4; nf++) {
                int bn = wn * 32 + nf * 8;
                bh[nf][0] = *(uint32_t*)&Bhi[(bn + r0) * ASTR + kb + cq];
                bh[nf][1] = *(uint32_t*)&Bhi[(bn + r0) * ASTR + kb + cq + 8];
                bl[nf][0] = *(uint32_t*)&Blo[(bn + r0) * ASTR + kb + cq];
                bl[nf][1] = *(uint32_t*)&Blo[(bn + r0) * ASTR + kb + cq + 8];
            }
#pragma unroll
            for (int mf = 0; mf < 4; mf++)
#pragma unroll
                for (int nf = 0; nf < 4; nf++) {
                    mma16816(acc[mf][nf], ah[mf], bh[nf]);
                    mma16816(acc[mf][nf], ah[mf], bl[nf]);
                    mma16816(acc[mf][nf], al[mf], bh[nf]);
                }
        }
        __syncthreads();
    }

    float rs = rsqrtf(1.f + 1e-5f);
#pragma unroll
    for (int mf = 0; mf < 4; mf++) {
        int o_r = o0 + wm * 64 + mf * 16 + (lane >> 2);
        float gn0 = g[o_r] * rs,     bo0 = bb[o_r];
        float gn1 = g[o_r + 8] * rs, bo1 = bb[o_r + 8];
        float m0 = 0.f, m1 = 0.f;
#pragma unroll
        for (int nf = 0; nf < 4; nf++) {
            m0 = fmaxf(m0, fmaxf(fmaf(gn0, acc[mf][nf][0], bo0), fmaf(gn0, acc[mf][nf][1], bo0)));
            m1 = fmaxf(m1, fmaxf(fmaf(gn1, acc[mf][nf][2], bo1), fmaf(gn1, acc[mf][nf][3], bo1)));
        }
        m0 = fmaxf(m0, 0.f); m1 = fmaxf(m1, 0.f);
#pragma unroll
        for (int off = 1; off <= 2; off <<= 1) {
            m0 = fmaxf(m0, __shfl_xor_sync(0xffffffffu, m0, off));
            m1 = fmaxf(m1, __shfl_xor_sync(0xffffffffu, m1, off));
        }
        if ((lane & 3) == 0) {
            atomicMax((int*)out + (size_t)b * 1024 + o_r,     __float_as_int(m0));
            atomicMax((int*)out + (size_t)b * 1024 + o_r + 8, __float_as_int(m1));
        }
    }
}

// ---------------- gather + max_k + bn + relu + fused bf16 hi/lo emit ----------------
__global__ __launch_bounds__(256) void gathermax_k(const float* __restrict__ y,
                                                   const float* __restrict__ z,
                                                   const int* __restrict__ idx,
                                                   const float* __restrict__ g,
                                                   const float* __restrict__ bb,
                                                   int O, float* __restrict__ out, size_t obs,
                                                   __nv_bfloat16* __restrict__ xhi,
                                                   __nv_bfloat16* __restrict__ xlo,
                                                   int outRow) {
    int b = blockIdx.z, n0 = blockIdx.y * 64, o0 = blockIdx.x * 4;
    __shared__ int sidx[64 * KNN];
    for (int e = threadIdx.x; e < 64 * KNN; e += 256) {
        int nl = e / KNN, kk = e % KNN;
        sidx[e] = idx[((size_t)(b * NP + n0 + nl)) * KNN + kk];
    }
    __syncthreads();
    int nl = threadIdx.x & 63, ol = threadIdx.x >> 6;
    int o = o0 + ol, n = n0 + nl;
    const float* yp = y + ((size_t)b * O + o) * NP;
    float m = NEG_INF;
#pragma unroll
    for (int kk = 0; kk < KNN; kk++) m = fmaxf(m, yp[sidx[nl * KNN + kk]]);
    float v = m + z[((size_t)b * O + o) * NP + n];
    float rs = rsqrtf(1.f + 1e-5f);
    v = fmaxf(fmaf(g[o] * rs, v, bb[o]), 0.f);
    out[(size_t)b * obs + (size_t)o * NP + n] = v;
    __nv_bfloat16 bh = __float2bfloat16_rn(v);
    __nv_bfloat16 bl = __float2bfloat16_rn(v - __bfloat162float(bh));
    size_t o2 = ((size_t)b * XROWS + outRow + o) * NP + n;
    xhi[o2] = bh;
    xlo[o2] = bl;
}

// ---------------- FC head ----------------
__global__ void fc_k(const float* __restrict__ in, int CI, const float* __restrict__ W,
                     int CO, const float* __restrict__ g, const float* __restrict__ bb,
                     float* __restrict__ out, int act) {
    int t = blockIdx.x * 256 + threadIdx.x;
    if (t >= BB * CO) return;
    int b = t / CO, j = t % CO;
    const float4* ip = (const float4*)(in + (size_t)b * CI);
    const float4* wp = (const float4*)(W + (size_t)j * CI);
    float s = 0.f;
    for (int c = 0; c < CI / 4; c++) {
        float4 a = ip[c], w = wp[c];
        s = fmaf(a.x, w.x, s); s = fmaf(a.y, w.y, s);
        s = fmaf(a.z, w.z, s); s = fmaf(a.w, w.w, s);
    }
    if (act) {
        float rs = rsqrtf(1.f + 1e-5f);
        s = fmaxf(fmaf(g[j] * rs, s, bb[j]), 0.f);
    }
    out[t] = s;
}

// ---------------- host side ----------------

static cudaStream_t s1 = nullptr;
static cudaEvent_t evF[4], evM[4];

static void edge_conv_launch(int li, const float* xin, size_t xbs, int C,
                             const float* W, int ldw, int O, int outRow,
                             const float* g, const float* bbp,
                             float* xc, float* y, float* z, float* sq, float* dist,
                             int* idxp, u64t* cand, unsigned* meta,
                             __nv_bfloat16* xhi, __nv_bfloat16* xlo) {
    cudaEventRecord(evF[li], 0);
    cudaStreamWaitEvent(s1, evF[li], 0);
    mmyz_k<<<dim3(NP / 128, O / 64, BB), 256, 0, s1>>>(xin, xbs, C, W, ldw, O, y, z);
    cudaEventRecord(evM[li], s1);

    sqnorm_k<<<(BB * NP + 255) / 256, 256>>>(xin, xbs, C, sq);
    dist2_k<<<dim3(136, 1, BB), 256>>>(xin, xbs, C, sq, dist);
    topkA_k<<<BB * NP, 256>>>(dist, idxp, cand, meta);
    topkB_k<<<BB * NP / 8, 256>>>(dist, cand, meta, idxp);

    cudaStreamWaitEvent(0, evM[li], 0);
    gathermax_k<<<dim3(O / 4, NP / 64, BB), 256>>>(y, z, idxp, g, bbp, O,
                                                   xc + (size_t)outRow * NP, (size_t)512 * NP,
                                                   xhi, xlo, outRow);
}

extern "C" void kernel_launch(void* const* d_in, const int* in_sizes, int n_in,
                              void* d_out, int out_size) {
    const float* x   = (const float*)d_in[0];
    const float* w1  = (const float*)d_in[1];
    const float* w2  = (const float*)d_in[2];
    const float* w3  = (const float*)d_in[3];
    const float* w4  = (const float*)d_in[4];
    const float* w5  = (const float*)d_in[5];
    const float* fw1 = (const float*)d_in[6];
    const float* fw2 = (const float*)d_in[7];
    const float* fw3 = (const float*)d_in[8];
    const float* g1 = (const float*)d_in[9],  *b1 = (const float*)d_in[10];
    const float* g2 = (const float*)d_in[11], *b2 = (const float*)d_in[12];
    const float* g3 = (const float*)d_in[13], *b3 = (const float*)d_in[14];
    const float* g4 = (const float*)d_in[15], *b4 = (const float*)d_in[16];
    const float* g5 = (const float*)d_in[17], *b5 = (const float*)d_in[18];
    const float* g6 = (const float*)d_in[19], *b6 = (const float*)d_in[20];
    const float* g7 = (const float*)d_in[21], *b7 = (const float*)d_in[22];

    float *xc, *y, *z, *sq, *dist, *hm, *h1, *h2;
    int* idxp;
    u64t* cand;
    unsigned* meta;
    __nv_bfloat16 *xhi, *xlo, *whi, *wlo;
    cudaGetSymbolAddress((void**)&xc,   g_xc);
    cudaGetSymbolAddress((void**)&y,    g_y);
    cudaGetSymbolAddress((void**)&z,    g_z);
    cudaGetSymbolAddress((void**)&sq,   g_sq);
    cudaGetSymbolAddress((void**)&dist, g_dist);
    cudaGetSymbolAddress((void**)&hm,   g_hm);
    cudaGetSymbolAddress((void**)&h1,   g_h1);
    cudaGetSymbolAddress((void**)&h2,   g_h2);
    cudaGetSymbolAddress((void**)&idxp, g_idx);
    cudaGetSymbolAddress((void**)&cand, g_cand);
    cudaGetSymbolAddress((void**)&meta, g_meta);
    cudaGetSymbolAddress((void**)&xhi,  g_xhi);
    cudaGetSymbolAddress((void**)&xlo,  g_xlo);
    cudaGetSymbolAddress((void**)&whi,  g_whi);
    cudaGetSymbolAddress((void**)&wlo,  g_wlo);

    if (!s1) {
        cudaStreamCreateWithFlags(&s1, cudaStreamNonBlocking);
        for (int i = 0; i < 4; i++) {
            cudaEventCreateWithFlags(&evF[i], cudaEventDisableTiming);
            cudaEventCreateWithFlags(&evM[i], cudaEventDisableTiming);
        }
    }

    zero_k<<<(BB * 1024 + 255) / 256, 256>>>(hm, BB * 1024);
    cvtw_k<<<(1024 * 512 / 4 + 255) / 256, 256>>>(w5, whi, wlo);

    edge_conv_launch(0, x,                     (size_t)3 * NP,   3,   w1, 6,   64,  0,
                     g1, b1, xc, y, z, sq, dist, idxp, cand, meta, xhi, xlo);
    edge_conv_launch(1, xc,                    (size_t)512 * NP, 64,  w2, 128, 64,  64,
                     g2, b2, xc, y, z, sq, dist, idxp, cand, meta, xhi, xlo);
    edge_conv_launch(2, xc + (size_t)64 * NP,  (size_t)512 * NP, 64,  w3, 128, 128, 128,
                     g3, b3, xc, y, z, sq, dist, idxp, cand, meta, xhi, xlo);
    edge_conv_launch(3, xc + (size_t)128 * NP, (size_t)512 * NP, 128, w4, 256, 256, 256,
                     g4, b4, xc, y, z, sq, dist, idxp, cand, meta, xhi, xlo);

    conv5_mma_k<<<dim3(NP / 128, 1024 / 128, BB), 256>>>(xhi, xlo, whi, wlo, g5, b5, hm);

    fc_k<<<(BB * 512 + 255) / 256, 256>>>(hm, 1024, fw1, 512, g6, b6, h1, 1);
    fc_k<<<(BB * 256 + 255) / 256, 256>>>(h1, 512, fw2, 256, g7, b7, h2, 1);
    fc_k<<<(BB * 40 + 255) / 256, 256>>>(h2, 256, fw3, 40, nullptr, nullptr, (float*)d_out, 0);
}

// round 16
// speedup vs baseline: 1.6951x; 1.0159x over previous
#include <cuda_runtime.h>
#include <cuda_bf16.h>
#include <cstdint>
#include <cstdio>

#define BB  8
#define NP  2048
#define KNN 20
#define NEG_INF (-3.4e38f)
#define ASTR 40
#define XROWS 512
#define CCAP 256

typedef unsigned long long u64t;

// ---------------- f32x2 packed-FMA helpers ----------------
__device__ __forceinline__ u64t pk2(float lo, float hi) {
    u64t d; asm("mov.b64 %0,{%1,%2};" : "=l"(d) : "f"(lo), "f"(hi)); return d;
}
__device__ __forceinline__ u64t fma2(u64t a, u64t b, u64t c) {
    u64t d; asm("fma.rn.f32x2 %0,%1,%2,%3;" : "=l"(d) : "l"(a), "l"(b), "l"(c)); return d;
}
__device__ __forceinline__ void upk2(u64t v, float& lo, float& hi) {
    asm("mov.b64 {%0,%1},%2;" : "=f"(lo), "=f"(hi) : "l"(v));
}

// ---------------- mma.sync helper (m16n8k16 bf16 -> f32) ----------------
__device__ __forceinline__ void mma16816(float* d, const uint32_t* a, const uint32_t* b) {
    asm volatile(
        "mma.sync.aligned.m16n8k16.row.col.f32.bf16.bf16.f32 "
        "{%0,%1,%2,%3},{%4,%5,%6,%7},{%8,%9},{%0,%1,%2,%3};"
        : "+f"(d[0]), "+f"(d[1]), "+f"(d[2]), "+f"(d[3])
        : "r"(a[0]), "r"(a[1]), "r"(a[2]), "r"(a[3]), "r"(b[0]), "r"(b[1]));
}
__device__ __forceinline__ void tpack(uint2 r0, uint2 r1, uint32_t* w) {
    w[0] = (r0.x & 0xffffu) | (r1.x << 16);
    w[1] = (r0.x >> 16)     | (r1.x & 0xffff0000u);
    w[2] = (r0.y & 0xffffu) | (r1.y << 16);
    w[3] = (r0.y >> 16)     | (r1.y & 0xffff0000u);
}
__device__ __forceinline__ unsigned monomap(float x) {
    unsigned bt = __float_as_uint(x);
    return (bt & 0x80000000u) ? ~bt : (bt | 0x80000000u);
}

// ---------------- scratch ----------------
__device__ float g_xc[(size_t)BB * 512 * NP];
__device__ float g_y [(size_t)BB * 256 * NP];
__device__ float g_z [(size_t)BB * 256 * NP];
__device__ int   g_idx[BB * NP * KNN];
__device__ float g_dist[(size_t)BB * NP * NP];
__device__ float g_part[(size_t)BB * 1024 * NP];       // conv5 split-K partials
__device__ u64t  g_cand[(size_t)BB * NP * CCAP];
__device__ unsigned g_meta[BB * NP];
__device__ float g_hm[BB * 1024];
__device__ float g_h1[BB * 512];
__device__ float g_h2[BB * 256];
__device__ __nv_bfloat16 g_xhi[(size_t)BB * XROWS * NP];
__device__ __nv_bfloat16 g_xlo[(size_t)BB * XROWS * NP];
__device__ __nv_bfloat16 g_whi[1024 * 512];
__device__ __nv_bfloat16 g_wlo[1024 * 512];

// ---------------- small kernels ----------------

__global__ void zero_k(float* p, int n) {
    int t = blockIdx.x * 256 + threadIdx.x;
    if (t < n) p[t] = 0.f;
}

__global__ void cvtw_k(const float* __restrict__ w,
                       __nv_bfloat16* __restrict__ whi, __nv_bfloat16* __restrict__ wlo) {
    int t = blockIdx.x * 256 + threadIdx.x;
    if (t >= 1024 * 512 / 4) return;
    float4 v = *(const float4*)&w[t * 4];
    float fv[4] = { v.x, v.y, v.z, v.w };
    unsigned short h[4], l[4];
#pragma unroll
    for (int q = 0; q < 4; q++) {
        __nv_bfloat16 bh = __float2bfloat16_rn(fv[q]);
        __nv_bfloat16 bl = __float2bfloat16_rn(fv[q] - __bfloat162float(bh));
        h[q] = *(unsigned short*)&bh;
        l[q] = *(unsigned short*)&bl;
    }
    *(uint2*)&whi[t * 4] = make_uint2((uint32_t)h[0] | ((uint32_t)h[1] << 16),
                                      (uint32_t)h[2] | ((uint32_t)h[3] << 16));
    *(uint2*)&wlo[t * 4] = make_uint2((uint32_t)l[0] | ((uint32_t)l[1] << 16),
                                      (uint32_t)l[2] | ((uint32_t)l[3] << 16));
}

// ---------------- dist: fp32 FFMA2, symmetric tiles, inlined sqnorm ----------------
__global__ __launch_bounds__(256) void dist2_k(const float* __restrict__ x, size_t xbs, int C,
                                               float* __restrict__ dist) {
    int b = blockIdx.z;
    int t = blockIdx.x;
    int j = (int)((sqrtf(8.f * t + 1.f) - 1.f) * 0.5f);
    while ((j + 1) * (j + 2) / 2 <= t) j++;
    while (j * (j + 1) / 2 > t) j--;
    int i = t - j * (j + 1) / 2;
    int n0 = i * 128, m0 = j * 128;

    __shared__ float As[16][128];
    __shared__ float Bs[16][128];
    __shared__ float sn_s[128], sm_s[128];
    int tid = threadIdx.x, tx = tid & 15, ty = tid >> 4;
    const float* xb = x + (size_t)b * xbs;

    // inlined sqnorm: threads 0-127 -> rows, 128-255 -> cols
    {
        float s = 0.f;
        int base = (tid < 128) ? (n0 + tid) : (m0 + tid - 128);
        for (int c = 0; c < C; c++) {
            float v = xb[(size_t)c * NP + base];
            s = fmaf(v, v, s);
        }
        if (tid < 128) sn_s[tid] = s; else sm_s[tid - 128] = s;
    }

    u64t acc2[8][4];
#pragma unroll
    for (int r = 0; r < 8; r++)
#pragma unroll
        for (int c = 0; c < 4; c++) acc2[r][c] = 0ull;

    for (int c0 = 0; c0 < C; c0 += 16) {
#pragma unroll
        for (int q = 0; q < 2; q++) {
            int e = tid + q * 256;
            int rr = e >> 5, c4 = (e & 31) * 4;
            float4 va = make_float4(0.f, 0.f, 0.f, 0.f);
            float4 vb = make_float4(0.f, 0.f, 0.f, 0.f);
            if (c0 + rr < C) {
                va = *(const float4*)&xb[(size_t)(c0 + rr) * NP + n0 + c4];
                vb = *(const float4*)&xb[(size_t)(c0 + rr) * NP + m0 + c4];
            }
            *(float4*)&As[rr][c4] = va;
            *(float4*)&Bs[rr][c4] = vb;
        }
        __syncthreads();
#pragma unroll
        for (int kk = 0; kk < 16; kk++) {
            float a[8];
#pragma unroll
            for (int r = 0; r < 8; r++) a[r] = As[kk][ty * 8 + r];
            u64t bv2[4];
#pragma unroll
            for (int c = 0; c < 4; c++) bv2[c] = *(const u64t*)&Bs[kk][tx * 8 + 2 * c];
#pragma unroll
            for (int r = 0; r < 8; r++) {
                u64t a2 = pk2(a[r], a[r]);
#pragma unroll
                for (int c = 0; c < 4; c++) acc2[r][c] = fma2(a2, bv2[c], acc2[r][c]);
            }
        }
        __syncthreads();
    }

    float acc[8][8];
#pragma unroll
    for (int r = 0; r < 8; r++)
#pragma unroll
        for (int c = 0; c < 4; c++) upk2(acc2[r][c], acc[r][2 * c], acc[r][2 * c + 1]);

    float sn[8], sm[8];
#pragma unroll
    for (int r = 0; r < 8; r++) sn[r] = sn_s[ty * 8 + r];
#pragma unroll
    for (int c = 0; c < 8; c++) sm[c] = sm_s[tx * 8 + c];
#pragma unroll
    for (int r = 0; r < 8; r++)
#pragma unroll
        for (int c = 0; c < 8; c++) acc[r][c] = 2.f * acc[r][c] - sn[r] - sm[c];

    float* dbase = dist + (size_t)b * NP * NP;
#pragma unroll
    for (int r = 0; r < 8; r++) {
        float* p = &dbase[(size_t)(n0 + ty * 8 + r) * NP + m0 + tx * 8];
        *(float4*)p       = *(float4*)&acc[r][0];
        *(float4*)(p + 4) = *(float4*)&acc[r][4];
    }
    if (i != j) {
#pragma unroll
        for (int c = 0; c < 8; c++) {
            float4 lo = make_float4(acc[0][c], acc[1][c], acc[2][c], acc[3][c]);
            float4 hi = make_float4(acc[4][c], acc[5][c], acc[6][c], acc[7][c]);
            float* p = &dbase[(size_t)(m0 + tx * 8 + c) * NP + n0 + ty * 8];
            *(float4*)p       = lo;
            *(float4*)(p + 4) = hi;
        }
    }
}

// ---------------- topk phase A ----------------
__global__ __launch_bounds__(256) void topkA_k(const float* __restrict__ dist,
                                               int* __restrict__ idxout,
                                               u64t* __restrict__ cand,
                                               unsigned* __restrict__ meta) {
    int r = blockIdx.x;
    const float* row = dist + (size_t)r * NP;
    int tid = threadIdx.x;
    float f[8];
    *(float4*)(f)     = *(const float4*)&row[tid * 8];
    *(float4*)(f + 4) = *(const float4*)&row[tid * 8 + 4];
    unsigned u[8];
#pragma unroll
    for (int q = 0; q < 8; q++) u[q] = monomap(f[q]);

    __shared__ unsigned hist[256];
    __shared__ int sh_hb, sh_need, sh_slot, sh_ecnt;
    hist[tid] = 0u;
    if (tid == 0) { sh_slot = 0; sh_ecnt = 0; }
    __syncthreads();
#pragma unroll
    for (int q = 0; q < 8; q++) atomicAdd(&hist[u[q] >> 24], 1u);
    __syncthreads();

    int lane = tid & 31, w = tid >> 5;
    if (w == 0) {
        int binbase = 255 - lane * 8;
        int h[8], s = 0;
#pragma unroll
        for (int q = 0; q < 8; q++) { h[q] = (int)hist[binbase - q]; s += h[q]; }
        int pre = s;
#pragma unroll
        for (int off = 1; off < 32; off <<= 1) {
            int o = __shfl_up_sync(0xffffffffu, pre, off);
            if (lane >= off) pre += o;
        }
        int excl = pre - s;
        if (excl < KNN && pre >= KNN) {
            int c = excl, q = 0;
            while (c + h[q] < KNN) { c += h[q]; q++; }
            sh_hb = binbase - q;
            sh_need = KNN - c;
        }
    }
    __syncthreads();

    int hb = sh_hb, base = r * KNN;
#pragma unroll
    for (int q = 0; q < 8; q++) {
        int hbq = (int)(u[q] >> 24);
        int idxv = tid * 8 + q;
        if (hbq > hb) {
            int s = atomicAdd(&sh_slot, 1);
            idxout[base + s] = idxv;
        } else if (hbq == hb) {
            int e = atomicAdd(&sh_ecnt, 1);
            if (e < CCAP)
                cand[(size_t)r * CCAP + e] = ((u64t)u[q] << 32) | (unsigned)(NP - 1 - idxv);
        }
    }
    __syncthreads();
    if (tid == 0)
        meta[r] = ((unsigned)hb << 24) | ((unsigned)sh_need << 16) | (unsigned)sh_ecnt;
}

// ---------------- topk phase B ----------------
__global__ __launch_bounds__(256) void topkB_k(const float* __restrict__ dist,
                                               const u64t* __restrict__ cand,
                                               const unsigned* __restrict__ meta,
                                               int* __restrict__ idxout) {
    int r = blockIdx.x * 8 + (threadIdx.x >> 5);
    int lane = threadIdx.x & 31;
    unsigned mt = meta[r];
    int hb = (int)(mt >> 24);
    int need = (int)((mt >> 16) & 0xffu);
    int ecnt = (int)(mt & 0xffffu);
    int wc = KNN - need;
    int base = r * KNN;

    if (ecnt <= CCAP) {
        const u64t* cp = cand + (size_t)r * CCAP;
        u64t v[8];
#pragma unroll
        for (int q = 0; q < 8; q++) {
            int i = lane + q * 32;
            v[q] = (i < ecnt) ? cp[i] : 0ull;
        }
        for (int it = 0; it < need; it++) {
            u64t best = 0ull;
#pragma unroll
            for (int q = 0; q < 8; q++) best = max(best, v[q]);
#pragma unroll
            for (int off = 16; off > 0; off >>= 1) {
                u64t o = __shfl_xor_sync(0xffffffffu, best, off);
                if (o > best) best = o;
            }
            if (lane == 0)
                idxout[base + wc + it] = NP - 1 - (int)(unsigned)(best & 0xffffffffu);
#pragma unroll
            for (int q = 0; q < 8; q++) if (v[q] == best) v[q] = 0ull;
        }
    } else {
        const float* row = dist + (size_t)r * NP;
        u64t prev = ~0ull;
        for (int it = 0; it < need; it++) {
            u64t best = 0ull;
            for (int i = lane; i < NP; i += 32) {
                unsigned uu = monomap(row[i]);
                if ((int)(uu >> 24) == hb) {
                    u64t key = ((u64t)uu << 32) | (unsigned)(NP - 1 - i);
                    if (key < prev && key > best) best = key;
                }
            }
#pragma unroll
            for (int off = 16; off > 0; off >>= 1) {
                u64t o = __shfl_xor_sync(0xffffffffu, best, off);
                if (o > best) best = o;
            }
            prev = best;
            if (lane == 0)
                idxout[base + wc + it] = NP - 1 - (int)(unsigned)(best & 0xffffffffu);
        }
    }
}

// ---------------- fused y+z GEMM (fp32 FFMA2) ----------------
__global__ __launch_bounds__(256) void mmyz_k(const float* __restrict__ X, size_t xbs, int C,
                                              const float* __restrict__ W, int ldw,
                                              int O, float* __restrict__ y,
                                              float* __restrict__ z) {
    int b = blockIdx.z, o0 = blockIdx.y * 64, n0 = blockIdx.x * 128;
    __shared__ float Wn[16][65];
    __shared__ float Wd[16][65];
    __shared__ float Xs[16][128];
    int tid = threadIdx.x, tx = tid & 15, ty = tid >> 4;
    const float* xb = X + (size_t)b * xbs;

    u64t accy[4][4], accz[4][4];
#pragma unroll
    for (int r = 0; r < 4; r++)
#pragma unroll
        for (int c = 0; c < 4; c++) { accy[r][c] = 0ull; accz[r][c] = 0ull; }

    for (int c0 = 0; c0 < C; c0 += 16) {
#pragma unroll
        for (int q = 0; q < 4; q++) {
            int e = tid + q * 256;
            int kk = e & 15, ol = e >> 4;
            int c = c0 + kk;
            float wn = 0.f, wd = 0.f;
            if (c < C) {
                const float* wr = W + (size_t)(o0 + ol) * ldw;
                wn = wr[c];
                wd = wr[C + c] - wn;
            }
            Wn[kk][ol] = wn;
            Wd[kk][ol] = wd;
        }
#pragma unroll
        for (int q = 0; q < 2; q++) {
            int e = tid + q * 256;
            int rr = e >> 5, c4 = (e & 31) * 4;
            float4 v = make_float4(0.f, 0.f, 0.f, 0.f);
            if (c0 + rr < C) v = *(const float4*)&xb[(size_t)(c0 + rr) * NP + n0 + c4];
            *(float4*)&Xs[rr][c4] = v;
        }
        __syncthreads();
#pragma unroll
        for (int kk = 0; kk < 16; kk++) {
            u64t bv2[4];
#pragma unroll
            for (int c = 0; c < 4; c++) bv2[c] = *(const u64t*)&Xs[kk][tx * 8 + 2 * c];
#pragma unroll
            for (int r = 0; r < 4; r++) {
                float an = Wn[kk][ty * 4 + r];
                float ad = Wd[kk][ty * 4 + r];
                u64t an2 = pk2(an, an);
                u64t ad2 = pk2(ad, ad);
#pragma unroll
                for (int c = 0; c < 4; c++) {
                    accy[r][c] = fma2(an2, bv2[c], accy[r][c]);
                    accz[r][c] = fma2(ad2, bv2[c], accz[r][c]);
                }
            }
        }
        __syncthreads();
    }

#pragma unroll
    for (int r = 0; r < 4; r++) {
        int o = o0 + ty * 4 + r;
        float ay[8], az[8];
#pragma unroll
        for (int c = 0; c < 4; c++) {
            upk2(accy[r][c], ay[2 * c], ay[2 * c + 1]);
            upk2(accz[r][c], az[2 * c], az[2 * c + 1]);
        }
        float* py = &y[((size_t)b * O + o) * NP + n0 + tx * 8];
        float* pz = &z[((size_t)b * O + o) * NP + n0 + tx * 8];
        *(float4*)py       = *(float4*)&ay[0];
        *(float4*)(py + 4) = *(float4*)&ay[4];
        *(float4*)pz       = *(float4*)&az[0];
        *(float4*)(pz + 4) = *(float4*)&az[4];
    }
}

// ---------------- conv5 via mma, split-K (cLo..cHi), 3-pass hi/lo ----------------
__global__ __launch_bounds__(256) void conv5_mma_k(const __nv_bfloat16* __restrict__ xhi,
                                                   const __nv_bfloat16* __restrict__ xlo,
                                                   const __nv_bfloat16* __restrict__ whi,
                                                   const __nv_bfloat16* __restrict__ wlo,
                                                   const float* __restrict__ g,
                                                   const float* __restrict__ bb,
                                                   float* __restrict__ out,
                                                   float* __restrict__ part,
                                                   int cLo, int cHi, int last) {
    __shared__ __nv_bfloat16 Ahi[128 * ASTR];
    __shared__ __nv_bfloat16 Alo[128 * ASTR];
    __shared__ __nv_bfloat16 Bhi[128 * ASTR];
    __shared__ __nv_bfloat16 Blo[128 * ASTR];

    int b = blockIdx.z, o0 = blockIdx.y * 128, n0 = blockIdx.x * 128;
    int tid = threadIdx.x, lane = tid & 31, wid = tid >> 5;
    int wm = wid >> 2, wn = wid & 3;
    const __nv_bfloat16* xh = xhi + (size_t)b * XROWS * NP;
    const __nv_bfloat16* xl = xlo + (size_t)b * XROWS * NP;

    float acc[4][4][4];
#pragma unroll
    for (int mf = 0; mf < 4; mf++)
#pragma unroll
        for (int nf = 0; nf < 4; nf++)
#pragma unroll
            for (int q = 0; q < 4; q++) acc[mf][nf][q] = 0.f;

    for (int c0 = cLo; c0 < cHi; c0 += 32) {
#pragma unroll
        for (int it = 0; it < 2; it++) {
            int e = tid + it * 256;
            int row = e >> 2, k8 = (e & 3) * 8;
            *(uint4*)&Ahi[row * ASTR + k8] = *(const uint4*)&whi[(size_t)(o0 + row) * 512 + c0 + k8];
            *(uint4*)&Alo[row * ASTR + k8] = *(const uint4*)&wlo[(size_t)(o0 + row) * 512 + c0 + k8];
        }
#pragma unroll
        for (int it = 0; it < 2; it++) {
            int e = tid + it * 256;
            int kp = e & 15, n4 = (e >> 4) * 4;
            int c = c0 + 2 * kp;
            uint2 bh  = *(const uint2*)&xh[(size_t)c * NP + n0 + n4];
            uint2 bl  = *(const uint2*)&xl[(size_t)c * NP + n0 + n4];
            uint2 b1h = *(const uint2*)&xh[(size_t)(c + 1) * NP + n0 + n4];
            uint2 b1l = *(const uint2*)&xl[(size_t)(c + 1) * NP + n0 + n4];
            uint32_t wb[4], wbl[4];
            tpack(bh, b1h, wb);
            tpack(bl, b1l, wbl);
#pragma unroll
            for (int q = 0; q < 4; q++) {
                *(uint32_t*)&Bhi[(n4 + q) * ASTR + 2 * kp] = wb[q];
                *(uint32_t*)&Blo[(n4 + q) * ASTR + 2 * kp] = wbl[q];
            }
        }
        __syncthreads();

        int r0 = lane >> 2, cq = (lane & 3) * 2;
#pragma unroll
        for (int ks = 0; ks < 2; ks++) {
            int kb = ks * 16;
            uint32_t ah[4][4], al[4][4], bh[4][2], bl[4][2];
#pragma unroll
            for (int mf = 0; mf < 4; mf++) {
                int am = wm * 64 + mf * 16;
                ah[mf][0] = *(uint32_t*)&Ahi[(am + r0) * ASTR + kb + cq];
                ah[mf][1] = *(uint32_t*)&Ahi[(am + r0 + 8) * ASTR + kb + cq];
                ah[mf][2] = *(uint32_t*)&Ahi[(am + r0) * ASTR + kb + cq + 8];
                ah[mf][3] = *(uint32_t*)&Ahi[(am + r0 + 8) * ASTR + kb + cq + 8];
                al[mf][0] = *(uint32_t*)&Alo[(am + r0) * ASTR + kb + cq];
                al[mf][1] = *(uint32_t*)&Alo[(am + r0 + 8) * ASTR + kb + cq];
                al[mf][2] = *(uint32_t*)&Alo[(am + r0) * ASTR + kb + cq + 8];
                al[mf][3] = *(uint32_t*)&Alo[(am + r0 + 8) * ASTR + kb + cq + 8];
            }
#pragma unroll
            for (int nf = 0; nf < 4; nf++) {
                int bn = wn * 32 + nf * 8;
                bh[nf][0] = *(uint32_t*)&Bhi[(bn + r0) * ASTR + kb + cq];
                bh[nf][1] = *(uint32_t*)&Bhi[(bn + r0) * ASTR + kb + cq + 8];
                bl[nf][0] = *(uint32_t*)&Blo[(bn + r0) * ASTR + kb + cq];
                bl[nf][1] = *(uint32_t*)&Blo[(bn + r0) * ASTR + kb + cq + 8];
            }
#pragma unroll
            for (int mf = 0; mf < 4; mf++)
#pragma unroll
                for (int nf = 0; nf < 4; nf++) {
                    mma16816(acc[mf][nf], ah[mf], bh[nf]);
                    mma16816(acc[mf][nf], ah[mf], bl[nf]);
                    mma16816(acc[mf][nf], al[mf], bh[nf]);
                }
        }
        __syncthreads();
    }

    int r0 = lane >> 2, cq = (lane & 3) * 2;
    if (!last) {
        // store fp32 partials
#pragma unroll
        for (int mf = 0; mf < 4; mf++) {
            int o_r = o0 + wm * 64 + mf * 16 + r0;
#pragma unroll
            for (int nf = 0; nf < 4; nf++) {
                int col = n0 + wn * 32 + nf * 8 + cq;
                *(float2*)&part[((size_t)b * 1024 + o_r) * NP + col] =
                    make_float2(acc[mf][nf][0], acc[mf][nf][1]);
                *(float2*)&part[((size_t)b * 1024 + o_r + 8) * NP + col] =
                    make_float2(acc[mf][nf][2], acc[mf][nf][3]);
            }
        }
        return;
    }

    // add partials, then bn+relu+max epilogue
#pragma unroll
    for (int mf = 0; mf < 4; mf++) {
        int o_r = o0 + wm * 64 + mf * 16 + r0;
#pragma unroll
        for (int nf = 0; nf < 4; nf++) {
            int col = n0 + wn * 32 + nf * 8 + cq;
            float2 p0 = *(const float2*)&part[((size_t)b * 1024 + o_r) * NP + col];
            float2 p1 = *(const float2*)&part[((size_t)b * 1024 + o_r + 8) * NP + col];
            acc[mf][nf][0] += p0.x; acc[mf][nf][1] += p0.y;
            acc[mf][nf][2] += p1.x; acc[mf][nf][3] += p1.y;
        }
    }
    float rs = rsqrtf(1.f + 1e-5f);
#pragma unroll
    for (int mf = 0; mf < 4; mf++) {
        int o_r = o0 + wm * 64 + mf * 16 + r0;
        float gn0 = g[o_r] * rs,     bo0 = bb[o_r];
        float gn1 = g[o_r + 8] * rs, bo1 = bb[o_r + 8];
        float m0 = 0.f, m1 = 0.f;
#pragma unroll
        for (int nf = 0; nf < 4; nf++) {
            m0 = fmaxf(m0, fmaxf(fmaf(gn0, acc[mf][nf][0], bo0), fmaf(gn0, acc[mf][nf][1], bo0)));
            m1 = fmaxf(m1, fmaxf(fmaf(gn1, acc[mf][nf][2], bo1), fmaf(gn1, acc[mf][nf][3], bo1)));
        }
        m0 = fmaxf(m0, 0.f); m1 = fmaxf(m1, 0.f);
#pragma unroll
        for (int off = 1; off <= 2; off <<= 1) {
            m0 = fmaxf(m0, __shfl_xor_sync(0xffffffffu, m0, off));
            m1 = fmaxf(m1, __shfl_xor_sync(0xffffffffu, m1, off));
        }
        if ((lane & 3) == 0) {
            atomicMax((int*)out + (size_t)b * 1024 + o_r,     __float_as_int(m0));
            atomicMax((int*)out + (size_t)b * 1024 + o_r + 8, __float_as_int(m1));
        }
    }
}

// ---------------- gather + max_k + bn + relu + fused bf16 hi/lo emit ----------------
__global__ __launch_bounds__(256) void gathermax_k(const float* __restrict__ y,
                                                   const float* __restrict__ z,
                                                   const int* __restrict__ idx,
                                                   const float* __restrict__ g,
                                                   const float* __restrict__ bb,
                                                   int O, float* __restrict__ out, size_t obs,
                                                   __nv_bfloat16* __restrict__ xhi,
                                                   __nv_bfloat16* __restrict__ xlo,
                                                   int outRow) {
    int b = blockIdx.z, n0 = blockIdx.y * 64, o0 = blockIdx.x * 4;
    __shared__ int sidx[64 * KNN];
    for (int e = threadIdx.x; e < 64 * KNN; e += 256) {
        int nl = e / KNN, kk = e % KNN;
        sidx[e] = idx[((size_t)(b * NP + n0 + nl)) * KNN + kk];
    }
    __syncthreads();
    int nl = threadIdx.x & 63, ol = threadIdx.x >> 6;
    int o = o0 + ol, n = n0 + nl;
    const float* yp = y + ((size_t)b * O + o) * NP;
    float m = NEG_INF;
#pragma unroll
    for (int kk = 0; kk < KNN; kk++) m = fmaxf(m, yp[sidx[nl * KNN + kk]]);
    float v = m + z[((size_t)b * O + o) * NP + n];
    float rs = rsqrtf(1.f + 1e-5f);
    v = fmaxf(fmaf(g[o] * rs, v, bb[o]), 0.f);
    out[(size_t)b * obs + (size_t)o * NP + n] = v;
    __nv_bfloat16 bh = __float2bfloat16_rn(v);
    __nv_bfloat16 bl = __float2bfloat16_rn(v - __bfloat162float(bh));
    size_t o2 = ((size_t)b * XROWS + outRow + o) * NP + n;
    xhi[o2] = bh;
    xlo[o2] = bl;
}

// ---------------- FC head ----------------
__global__ void fc_k(const float* __restrict__ in, int CI, const float* __restrict__ W,
                     int CO, const float* __restrict__ g, const float* __restrict__ bb,
                     float* __restrict__ out, int act) {
    int t = blockIdx.x * 256 + threadIdx.x;
    if (t >= BB * CO) return;
    int b = t / CO, j = t % CO;
    const float4* ip = (const float4*)(in + (size_t)b * CI);
    const float4* wp = (const float4*)(W + (size_t)j * CI);
    float s = 0.f;
    for (int c = 0; c < CI / 4; c++) {
        float4 a = ip[c], w = wp[c];
        s = fmaf(a.x, w.x, s); s = fmaf(a.y, w.y, s);
        s = fmaf(a.z, w.z, s); s = fmaf(a.w, w.w, s);
    }
    if (act) {
        float rs = rsqrtf(1.f + 1e-5f);
        s = fmaxf(fmaf(g[j] * rs, s, bb[j]), 0.f);
    }
    out[t] = s;
}

// ---------------- host side ----------------

static cudaStream_t s1 = nullptr, s2 = nullptr;
static cudaEvent_t evF[4], evM[4], evG3, evC5;

static void edge_conv_launch(int li, const float* xin, size_t xbs, int C,
                             const float* W, int ldw, int O, int outRow,
                             const float* g, const float* bbp,
                             float* xc, float* y, float* z, float* dist,
                             int* idxp, u64t* cand, unsigned* meta,
                             __nv_bfloat16* xhi, __nv_bfloat16* xlo) {
    cudaEventRecord(evF[li], 0);
    cudaStreamWaitEvent(s1, evF[li], 0);
    mmyz_k<<<dim3(NP / 128, O / 64, BB), 256, 0, s1>>>(xin, xbs, C, W, ldw, O, y, z);
    cudaEventRecord(evM[li], s1);

    dist2_k<<<dim3(136, 1, BB), 256>>>(xin, xbs, C, dist);
    topkA_k<<<BB * NP, 256>>>(dist, idxp, cand, meta);
    topkB_k<<<BB * NP / 8, 256>>>(dist, cand, meta, idxp);

    cudaStreamWaitEvent(0, evM[li], 0);
    gathermax_k<<<dim3(O / 4, NP / 64, BB), 256>>>(y, z, idxp, g, bbp, O,
                                                   xc + (size_t)outRow * NP, (size_t)512 * NP,
                                                   xhi, xlo, outRow);
}

extern "C" void kernel_launch(void* const* d_in, const int* in_sizes, int n_in,
                              void* d_out, int out_size) {
    const float* x   = (const float*)d_in[0];
    const float* w1  = (const float*)d_in[1];
    const float* w2  = (const float*)d_in[2];
    const float* w3  = (const float*)d_in[3];
    const float* w4  = (const float*)d_in[4];
    const float* w5  = (const float*)d_in[5];
    const float* fw1 = (const float*)d_in[6];
    const float* fw2 = (const float*)d_in[7];
    const float* fw3 = (const float*)d_in[8];
    const float* g1 = (const float*)d_in[9],  *b1 = (const float*)d_in[10];
    const float* g2 = (const float*)d_in[11], *b2 = (const float*)d_in[12];
    const float* g3 = (const float*)d_in[13], *b3 = (const float*)d_in[14];
    const float* g4 = (const float*)d_in[15], *b4 = (const float*)d_in[16];
    const float* g5 = (const float*)d_in[17], *b5 = (const float*)d_in[18];
    const float* g6 = (const float*)d_in[19], *b6 = (const float*)d_in[20];
    const float* g7 = (const float*)d_in[21], *b7 = (const float*)d_in[22];

    float *xc, *y, *z, *dist, *part, *hm, *h1, *h2;
    int* idxp;
    u64t* cand;
    unsigned* meta;
    __nv_bfloat16 *xhi, *xlo, *whi, *wlo;
    cudaGetSymbolAddress((void**)&xc,   g_xc);
    cudaGetSymbolAddress((void**)&y,    g_y);
    cudaGetSymbolAddress((void**)&z,    g_z);
    cudaGetSymbolAddress((void**)&dist, g_dist);
    cudaGetSymbolAddress((void**)&part, g_part);
    cudaGetSymbolAddress((void**)&hm,   g_hm);
    cudaGetSymbolAddress((void**)&h1,   g_h1);
    cudaGetSymbolAddress((void**)&h2,   g_h2);
    cudaGetSymbolAddress((void**)&idxp, g_idx);
    cudaGetSymbolAddress((void**)&cand, g_cand);
    cudaGetSymbolAddress((void**)&meta, g_meta);
    cudaGetSymbolAddress((void**)&xhi,  g_xhi);
    cudaGetSymbolAddress((void**)&xlo,  g_xlo);
    cudaGetSymbolAddress((void**)&whi,  g_whi);
    cudaGetSymbolAddress((void**)&wlo,  g_wlo);

    if (!s1) {
        cudaStreamCreateWithFlags(&s1, cudaStreamNonBlocking);
        cudaStreamCreateWithFlags(&s2, cudaStreamNonBlocking);
        for (int i = 0; i < 4; i++) {
            cudaEventCreateWithFlags(&evF[i], cudaEventDisableTiming);
            cudaEventCreateWithFlags(&evM[i], cudaEventDisableTiming);
        }
        cudaEventCreateWithFlags(&evG3, cudaEventDisableTiming);
        cudaEventCreateWithFlags(&evC5, cudaEventDisableTiming);
    }

    zero_k<<<(BB * 1024 + 255) / 256, 256>>>(hm, BB * 1024);
    cvtw_k<<<(1024 * 512 / 4 + 255) / 256, 256>>>(w5, whi, wlo);

    edge_conv_launch(0, x,                     (size_t)3 * NP,   3,   w1, 6,   64,  0,
                     g1, b1, xc, y, z, dist, idxp, cand, meta, xhi, xlo);
    edge_conv_launch(1, xc,                    (size_t)512 * NP, 64,  w2, 128, 64,  64,
                     g2, b2, xc, y, z, dist, idxp, cand, meta, xhi, xlo);
    edge_conv_launch(2, xc + (size_t)64 * NP,  (size_t)512 * NP, 64,  w3, 128, 128, 128,
                     g3, b3, xc, y, z, dist, idxp, cand, meta, xhi, xlo);

    // conv5 half1 (c 0..255: layers 1-3 features) overlapped with layer-4 chain on s2
    cudaEventRecord(evG3, 0);
    cudaStreamWaitEvent(s2, evG3, 0);
    conv5_mma_k<<<dim3(NP / 128, 1024 / 128, BB), 256, 0, s2>>>(
        xhi, xlo, whi, wlo, g5, b5, hm, part, 0, 256, 0);
    cudaEventRecord(evC5, s2);

    edge_conv_launch(3, xc + (size_t)128 * NP, (size_t)512 * NP, 128, w4, 256, 256, 256,
                     g4, b4, xc, y, z, dist, idxp, cand, meta, xhi, xlo);

    // conv5 half2 (c 256..511) + partial add + epilogue
    cudaStreamWaitEvent(0, evC5, 0);
    conv5_mma_k<<<dim3(NP / 128, 1024 / 128, BB), 256>>>(
        xhi, xlo, whi, wlo, g5, b5, hm, part, 256, 512, 1);

    fc_k<<<(BB * 512 + 255) / 256, 256>>>(hm, 1024, fw1, 512, g6, b6, h1, 1);
    fc_k<<<(BB * 256 + 255) / 256, 256>>>(h1, 512, fw2, 256, g7, b7, h2, 1);
    fc_k<<<(BB * 40 + 255) / 256, 256>>>(h2, 256, fw3, 40, nullptr, nullptr, (float*)d_out, 0);
}